// round 8
// baseline (speedup 1.0000x reference)
#include <cuda_runtime.h>
#include <math.h>
#include <stdint.h>

// Problem constants
#define BATCH   4
#define SEQLEN  2048
#define DMODEL  1024
#define NHEAD   16
#define HEADDIM 64
#define MROWS   (BATCH * SEQLEN)   // 8192

// Scratch (device globals: no allocation allowed in kernel_launch)
__device__ float g_q[(size_t)BATCH * NHEAD * SEQLEN * HEADDIM];    // [B,H,L,hd]
__device__ float g_k[(size_t)BATCH * NHEAD * SEQLEN * HEADDIM];
__device__ float g_v[(size_t)BATCH * NHEAD * SEQLEN * HEADDIM];
__device__ float g_attn[(size_t)MROWS * DMODEL];                   // [B,L,H*hd]

// ---------------------------------------------------------------------------
// TF32 mma helpers
// ---------------------------------------------------------------------------
__device__ __forceinline__ uint32_t f2tf32(float f) {
    uint32_t u;
    asm("cvt.rna.tf32.f32 %0, %1;" : "=r"(u) : "f"(f));
    return u;
}

__device__ __forceinline__ void mma_tf32(float* d, const uint32_t* a,
                                         uint32_t b0, uint32_t b1) {
    asm volatile(
        "mma.sync.aligned.m16n8k8.row.col.f32.tf32.tf32.f32 "
        "{%0,%1,%2,%3}, {%4,%5,%6,%7}, {%8,%9}, {%0,%1,%2,%3};\n"
        : "+f"(d[0]), "+f"(d[1]), "+f"(d[2]), "+f"(d[3])
        : "r"(a[0]), "r"(a[1]), "r"(a[2]), "r"(a[3]), "r"(b0), "r"(b1));
}

// ---------------------------------------------------------------------------
// TF32 GEMM: C[m,n] = sum_k A[m,k] * W[n,k] + bias[n]
// Block 128x128, BK=32, 256 threads (8 warps as 4m x 2n), warp tile 32x64.
// 64-wide head-aligned warp n-tile => RoPE partner (d, d+32) is in-thread.
// sel 0: -> g_q scatter [B,H,L,hd], RoPE + 1/8 scale fused in epilogue
// sel 1: -> g_k scatter, RoPE fused
// sel 2: -> g_v scatter, plain
// sel 3: A = g_attn -> C_out row-major [M, DMODEL], plain
// ---------------------------------------------------------------------------
__global__ __launch_bounds__(256) void gemm_tf32(const float* __restrict__ A_in,
                                                 const float* __restrict__ W,
                                                 const float* __restrict__ bias,
                                                 float* __restrict__ C_out,
                                                 int sel)
{
    __shared__ float As[128][36];
    __shared__ float Ws[128][36];

    const int K = DMODEL;
    const float* A = (sel == 3) ? g_attn : A_in;
    float* C;
    if (sel == 0)      C = g_q;
    else if (sel == 1) C = g_k;
    else if (sel == 2) C = g_v;
    else               C = C_out;

    const int tid  = threadIdx.x;
    const int w    = tid >> 5;
    const int lane = tid & 31;
    const int g    = lane >> 2;
    const int q    = lane & 3;
    const int wm   = (w & 3) * 32;     // warp m-offset (4 positions)
    const int wn   = (w >> 2) * 64;    // warp n-offset (2 positions, head-aligned)

    const int m0 = blockIdx.y * 128;
    const int n0 = blockIdx.x * 128;

    const float* Aptr = A + (size_t)m0 * K;
    const float* Wptr = W + (size_t)n0 * K;

    // Global-load mapping: idx = tid + i*256 in [0,1024); row=idx>>3, c4=(idx&7)*4
    int ld_row[4], ld_c4[4];
#pragma unroll
    for (int i = 0; i < 4; i++) {
        int idx = tid + i * 256;
        ld_row[i] = idx >> 3;
        ld_c4[i]  = (idx & 7) * 4;
    }

    float acc[2][8][4];
#pragma unroll
    for (int mi = 0; mi < 2; mi++)
#pragma unroll
        for (int nj = 0; nj < 8; nj++)
#pragma unroll
            for (int c = 0; c < 4; c++) acc[mi][nj][c] = 0.0f;

    // Prefetch tile 0
    float4 pa[4], pw[4];
#pragma unroll
    for (int i = 0; i < 4; i++) {
        pa[i] = *reinterpret_cast<const float4*>(Aptr + (size_t)ld_row[i] * K + ld_c4[i]);
        pw[i] = *reinterpret_cast<const float4*>(Wptr + (size_t)ld_row[i] * K + ld_c4[i]);
    }

    for (int kt = 0; kt < K; kt += 32) {
#pragma unroll
        for (int i = 0; i < 4; i++) {
            float4 a = pa[i], t;
            t.x = __uint_as_float(f2tf32(a.x));
            t.y = __uint_as_float(f2tf32(a.y));
            t.z = __uint_as_float(f2tf32(a.z));
            t.w = __uint_as_float(f2tf32(a.w));
            *reinterpret_cast<float4*>(&As[ld_row[i]][ld_c4[i]]) = t;
            float4 b = pw[i];
            t.x = __uint_as_float(f2tf32(b.x));
            t.y = __uint_as_float(f2tf32(b.y));
            t.z = __uint_as_float(f2tf32(b.z));
            t.w = __uint_as_float(f2tf32(b.w));
            *reinterpret_cast<float4*>(&Ws[ld_row[i]][ld_c4[i]]) = t;
        }
        __syncthreads();

        if (kt + 32 < K) {
#pragma unroll
            for (int i = 0; i < 4; i++) {
                pa[i] = *reinterpret_cast<const float4*>(
                    Aptr + (size_t)ld_row[i] * K + kt + 32 + ld_c4[i]);
                pw[i] = *reinterpret_cast<const float4*>(
                    Wptr + (size_t)ld_row[i] * K + kt + 32 + ld_c4[i]);
            }
        }

#pragma unroll
        for (int kc = 0; kc < 4; kc++) {
            const int k0 = kc * 8;
            uint32_t a[2][4];
#pragma unroll
            for (int mi = 0; mi < 2; mi++) {
                int r = wm + mi * 16;
                a[mi][0] = __float_as_uint(As[r + g][k0 + q]);
                a[mi][1] = __float_as_uint(As[r + 8 + g][k0 + q]);
                a[mi][2] = __float_as_uint(As[r + g][k0 + q + 4]);
                a[mi][3] = __float_as_uint(As[r + 8 + g][k0 + q + 4]);
            }
            uint32_t b[8][2];
#pragma unroll
            for (int nj = 0; nj < 8; nj++) {
                int bn = wn + nj * 8;
                b[nj][0] = __float_as_uint(Ws[bn + g][k0 + q]);
                b[nj][1] = __float_as_uint(Ws[bn + g][k0 + q + 4]);
            }
#pragma unroll
            for (int mi = 0; mi < 2; mi++)
#pragma unroll
                for (int nj = 0; nj < 8; nj++)
                    mma_tf32(acc[mi][nj], a[mi], b[nj][0], b[nj][1]);
        }
        __syncthreads();
    }

    // ---- Epilogue ----
    if (sel <= 1) {
        // Q/K: fused RoPE (warp n-tile head-aligned; pair = (nj, nj+4)).
        const float cfrq  = 9.210340371976184f / 32.0f;   // ln(10000)/32
        const float scale = (sel == 0) ? 0.125f : 1.0f;
#pragma unroll
        for (int nj = 0; nj < 4; nj++) {
            int cn = n0 + wn + nj * 8 + 2 * q;   // lo column
            int d0 = cn & 63;                    // < 32
            int h_ = cn >> 6;
            float if0 = __expf(-(float)d0 * cfrq);
            float if1 = __expf(-(float)(d0 + 1) * cfrq);
            float bl0 = bias[cn],      bl1 = bias[cn + 1];
            float bh0 = bias[cn + 32], bh1 = bias[cn + 33];
#pragma unroll
            for (int mi = 0; mi < 2; mi++) {
#pragma unroll
                for (int rr = 0; rr < 2; rr++) {
                    int m  = m0 + wm + mi * 16 + g + rr * 8;
                    int b_ = m >> 11, l_ = m & 2047;
                    float lo0 = acc[mi][nj][rr * 2 + 0] + bl0;
                    float lo1 = acc[mi][nj][rr * 2 + 1] + bl1;
                    float hi0 = acc[mi][nj + 4][rr * 2 + 0] + bh0;
                    float hi1 = acc[mi][nj + 4][rr * 2 + 1] + bh1;
                    float sn0, cs0, sn1, cs1;
                    sincosf((float)l_ * if0, &sn0, &cs0);
                    sincosf((float)l_ * if1, &sn1, &cs1);
                    float2 vlo = make_float2((lo0 * cs0 - hi0 * sn0) * scale,
                                             (lo1 * cs1 - hi1 * sn1) * scale);
                    float2 vhi = make_float2((hi0 * cs0 + lo0 * sn0) * scale,
                                             (hi1 * cs1 + lo1 * sn1) * scale);
                    size_t base = (((size_t)(b_ * NHEAD + h_)) * SEQLEN + l_) * HEADDIM;
                    *reinterpret_cast<float2*>(C + base + d0)      = vlo;
                    *reinterpret_cast<float2*>(C + base + d0 + 32) = vhi;
                }
            }
        }
    } else {
#pragma unroll
        for (int nj = 0; nj < 8; nj++) {
            int cn = n0 + wn + nj * 8 + 2 * q;
            float b0 = bias[cn];
            float b1 = bias[cn + 1];
#pragma unroll
            for (int mi = 0; mi < 2; mi++) {
#pragma unroll
                for (int rr = 0; rr < 2; rr++) {
                    int m  = m0 + wm + mi * 16 + g + rr * 8;
                    float2 v = make_float2(acc[mi][nj][rr * 2 + 0] + b0,
                                           acc[mi][nj][rr * 2 + 1] + b1);
                    if (sel == 2) {
                        int h_ = cn >> 6;
                        int d_ = cn & 63;
                        int b_ = m >> 11, l_ = m & 2047;
                        *reinterpret_cast<float2*>(
                            C + (((size_t)(b_ * NHEAD + h_)) * SEQLEN + l_) * HEADDIM + d_) = v;
                    } else {
                        *reinterpret_cast<float2*>(C + (size_t)m * DMODEL + cn) = v;
                    }
                }
            }
        }
    }
}

// ---------------------------------------------------------------------------
// Flash attention, tf32 mma, RoPE precomputed (in GEMM epilogue).
// Grid: (L/128, B*H). Block: 256 threads (8 warps), 1 m-frag per warp.
// K stored pair-interleaved by column (col' = kc*8 + 2q + h, h: d or d+32...
// actually h selects d = kc*8+q vs kc*8+q+4) -> one LDS.64 per B-frag.
// V stored pair-interleaved by row (rows kc*8+q / kc*8+q+4 merged) likewise.
// ---------------------------------------------------------------------------
__global__ __launch_bounds__(256, 2) void attn_mma_kernel()
{
    // Kp[64][72] (4608 fl) + Vp[32][136] (4352 fl) = 8960 floats = 35840 B
    __shared__ float smem_all[64 * 72 + 32 * 136];
    float (*Kp)[72]  = (float(*)[72])smem_all;
    float (*Vp)[136] = (float(*)[136])(smem_all + 64 * 72);
    float (*Qs)[68]  = (float(*)[68])smem_all;   // 128*68 = 8704 <= 8960 (staging)

    const int tid  = threadIdx.x;
    const int w    = tid >> 5;
    const int lane = tid & 31;
    const int g    = lane >> 2;
    const int q    = lane & 3;

    const int bh = blockIdx.y;
    const int b_ = bh >> 4;
    const int h_ = bh & 15;
    const int q0 = blockIdx.x * 128;

    const float* Qg = g_q + (size_t)bh * SEQLEN * HEADDIM;
    const float* Kg = g_k + (size_t)bh * SEQLEN * HEADDIM;
    const float* Vg = g_v + (size_t)bh * SEQLEN * HEADDIM;

    // ---- Load Q tile [128][64] (already RoPE'd + scaled) ----
#pragma unroll
    for (int i = 0; i < 8; i++) {
        int idx = tid + i * 256;
        int r = idx >> 4;
        int cv = (idx & 15) * 4;
        float4 v = *reinterpret_cast<const float4*>(Qg + (size_t)(q0 + r) * HEADDIM + cv);
        Qs[r][cv + 0] = v.x; Qs[r][cv + 1] = v.y;
        Qs[r][cv + 2] = v.z; Qs[r][cv + 3] = v.w;
    }
    __syncthreads();

    // ---- Extract Q A-fragment (1 m-frag per warp) ----
    uint32_t aq[8][4];
    {
        int row0 = w * 16 + g;
#pragma unroll
        for (int kc = 0; kc < 8; kc++) {
            int c0 = kc * 8 + q;
            aq[kc][0] = f2tf32(Qs[row0][c0]);
            aq[kc][1] = f2tf32(Qs[row0 + 8][c0]);
            aq[kc][2] = f2tf32(Qs[row0][c0 + 4]);
            aq[kc][3] = f2tf32(Qs[row0 + 8][c0 + 4]);
        }
    }

    float o[8][4];
    float mA = -INFINITY, mB = -INFINITY, lA = 0.0f, lB = 0.0f;
#pragma unroll
    for (int n = 0; n < 8; n++)
#pragma unroll
        for (int c = 0; c < 4; c++) o[n][c] = 0.0f;

    for (int kk = 0; kk < 32; kk++) {
        const int kv0 = kk * 64;
        __syncthreads();   // kk=0: Q frags extracted; kk>0: prior mma reads done

        // ---- Load K, V tiles into paired layouts (tf32-converted) ----
#pragma unroll
        for (int i = 0; i < 4; i++) {
            int idx = tid + i * 256;
            int r = idx >> 4;              // 0..63
            int cv = (idx & 15) * 4;       // 0..60, aligned 4
            float4 kv = *reinterpret_cast<const float4*>(Kg + (size_t)(kv0 + r) * HEADDIM + cv);
            // K: col' = (d & ~7) + 2*(d&3) + ((d&4)>>2); d = cv+j, j<4 => d&3=j
            int kb = (cv & ~7) + ((cv & 4) >> 2);
            Kp[r][kb + 0] = __uint_as_float(f2tf32(kv.x));
            Kp[r][kb + 2] = __uint_as_float(f2tf32(kv.y));
            Kp[r][kb + 4] = __uint_as_float(f2tf32(kv.z));
            Kp[r][kb + 6] = __uint_as_float(f2tf32(kv.w));
            float4 vv = *reinterpret_cast<const float4*>(Vg + (size_t)(kv0 + r) * HEADDIM + cv);
            // V: row r = kc*8 + q + 4h -> Vp[kc*4+q][2c+h]
            int vrow = ((r >> 3) << 2) + (r & 3);
            int vh   = (r >> 2) & 1;
            Vp[vrow][2 * (cv + 0) + vh] = __uint_as_float(f2tf32(vv.x));
            Vp[vrow][2 * (cv + 1) + vh] = __uint_as_float(f2tf32(vv.y));
            Vp[vrow][2 * (cv + 2) + vh] = __uint_as_float(f2tf32(vv.z));
            Vp[vrow][2 * (cv + 3) + vh] = __uint_as_float(f2tf32(vv.w));
        }
        __syncthreads();

        // ---- S = Q . K^T  (m16n8k8 tf32); B-frag = one LDS.64 ----
        float s[8][4];
#pragma unroll
        for (int n = 0; n < 8; n++)
#pragma unroll
            for (int c = 0; c < 4; c++) s[n][c] = 0.0f;

#pragma unroll
        for (int n = 0; n < 8; n++) {
#pragma unroll
            for (int kc = 0; kc < 8; kc++) {
                float2 bb = *reinterpret_cast<const float2*>(&Kp[n * 8 + g][kc * 8 + 2 * q]);
                mma_tf32(s[n], aq[kc], __float_as_uint(bb.x), __float_as_uint(bb.y));
            }
        }

        // ---- Online softmax ----
        {
            float mxA = -1e30f, mxB = -1e30f;
#pragma unroll
            for (int n = 0; n < 8; n++) {
                mxA = fmaxf(mxA, fmaxf(s[n][0], s[n][1]));
                mxB = fmaxf(mxB, fmaxf(s[n][2], s[n][3]));
            }
            mxA = fmaxf(mxA, __shfl_xor_sync(0xffffffffu, mxA, 1));
            mxA = fmaxf(mxA, __shfl_xor_sync(0xffffffffu, mxA, 2));
            mxB = fmaxf(mxB, __shfl_xor_sync(0xffffffffu, mxB, 1));
            mxB = fmaxf(mxB, __shfl_xor_sync(0xffffffffu, mxB, 2));
            float mnA = fmaxf(mA, mxA);
            float mnB = fmaxf(mB, mxB);
            float cA = __expf(mA - mnA);
            float cB = __expf(mB - mnB);
            float rsA = 0.0f, rsB = 0.0f;
#pragma unroll
            for (int n = 0; n < 8; n++) {
                s[n][0] = __expf(s[n][0] - mnA); rsA += s[n][0];
                s[n][1] = __expf(s[n][1] - mnA); rsA += s[n][1];
                s[n][2] = __expf(s[n][2] - mnB); rsB += s[n][2];
                s[n][3] = __expf(s[n][3] - mnB); rsB += s[n][3];
                o[n][0] *= cA; o[n][1] *= cA;
                o[n][2] *= cB; o[n][3] *= cB;
            }
            rsA += __shfl_xor_sync(0xffffffffu, rsA, 1);
            rsA += __shfl_xor_sync(0xffffffffu, rsA, 2);
            rsB += __shfl_xor_sync(0xffffffffu, rsB, 1);
            rsB += __shfl_xor_sync(0xffffffffu, rsB, 2);
            lA = lA * cA + rsA; mA = mnA;
            lB = lB * cB + rsB; mB = mnB;
        }

        // ---- O += P . V : P A-frags via shfl; V B-frag = one LDS.64 ----
        const int src0 = (g << 2) + (q >> 1);
        const int src1 = src0 + 2;
        const bool odd = (q & 1);
#pragma unroll
        for (int kc = 0; kc < 8; kc++) {
            uint32_t ap[4];
            float v00 = __shfl_sync(0xffffffffu, s[kc][0], src0);
            float v01 = __shfl_sync(0xffffffffu, s[kc][1], src0);
            float v02 = __shfl_sync(0xffffffffu, s[kc][2], src0);
            float v03 = __shfl_sync(0xffffffffu, s[kc][3], src0);
            float v10 = __shfl_sync(0xffffffffu, s[kc][0], src1);
            float v11 = __shfl_sync(0xffffffffu, s[kc][1], src1);
            float v12 = __shfl_sync(0xffffffffu, s[kc][2], src1);
            float v13 = __shfl_sync(0xffffffffu, s[kc][3], src1);
            ap[0] = f2tf32(odd ? v01 : v00);
            ap[1] = f2tf32(odd ? v03 : v02);
            ap[2] = f2tf32(odd ? v11 : v10);
            ap[3] = f2tf32(odd ? v13 : v12);
#pragma unroll
            for (int n = 0; n < 8; n++) {
                float2 bb = *reinterpret_cast<const float2*>(&Vp[kc * 4 + q][2 * (n * 8 + g)]);
                mma_tf32(o[n], ap, __float_as_uint(bb.x), __float_as_uint(bb.y));
            }
        }
    }

    // ---- Epilogue: normalize, write [B,L,H*hd] ----
    {
        float iA = 1.0f / lA;
        float iB = 1.0f / lB;
        int row0 = q0 + w * 16 + g;
#pragma unroll
        for (int n = 0; n < 8; n++) {
            int col = n * 8 + 2 * q;
            float2 r0v = make_float2(o[n][0] * iA, o[n][1] * iA);
            float2 r1v = make_float2(o[n][2] * iB, o[n][3] * iB);
            *reinterpret_cast<float2*>(
                g_attn + ((size_t)(b_ * SEQLEN + row0) * NHEAD + h_) * HEADDIM + col) = r0v;
            *reinterpret_cast<float2*>(
                g_attn + ((size_t)(b_ * SEQLEN + row0 + 8) * NHEAD + h_) * HEADDIM + col) = r1v;
        }
    }
}

// ---------------------------------------------------------------------------
extern "C" void kernel_launch(void* const* d_in, const int* in_sizes, int n_in,
                              void* d_out, int out_size)
{
    const float* x  = (const float*)d_in[0];
    const float* Wq = (const float*)d_in[1];
    const float* bq = (const float*)d_in[2];
    const float* Wk = (const float*)d_in[3];
    const float* bk = (const float*)d_in[4];
    const float* Wv = (const float*)d_in[5];
    const float* bv = (const float*)d_in[6];
    const float* Wo = (const float*)d_in[7];
    const float* bo = (const float*)d_in[8];
    float* out = (float*)d_out;

    dim3 ggrid(DMODEL / 128, MROWS / 128);   // (8, 64)
    gemm_tf32<<<ggrid, 256>>>(x, Wq, bq, nullptr, 0);
    gemm_tf32<<<ggrid, 256>>>(x, Wk, bk, nullptr, 1);
    gemm_tf32<<<ggrid, 256>>>(x, Wv, bv, nullptr, 2);

    attn_mma_kernel<<<dim3(SEQLEN / 128, BATCH * NHEAD), 256>>>();

    gemm_tf32<<<ggrid, 256>>>(nullptr, Wo, bo, out, 3);
}

// round 9
// speedup vs baseline: 1.2130x; 1.2130x over previous
#include <cuda_runtime.h>
#include <math.h>
#include <stdint.h>

// Problem constants
#define BATCH   4
#define SEQLEN  2048
#define DMODEL  1024
#define NHEAD   16
#define HEADDIM 64
#define MROWS   (BATCH * SEQLEN)   // 8192

// Scratch (device globals: no allocation allowed in kernel_launch)
__device__ float g_q[(size_t)BATCH * NHEAD * SEQLEN * HEADDIM];    // [B,H,L,hd]
__device__ float g_k[(size_t)BATCH * NHEAD * SEQLEN * HEADDIM];
__device__ float g_v[(size_t)BATCH * NHEAD * SEQLEN * HEADDIM];
__device__ float g_attn[(size_t)MROWS * DMODEL];                   // [B,L,H*hd]

// ---------------------------------------------------------------------------
// TF32 mma helpers
// ---------------------------------------------------------------------------
__device__ __forceinline__ uint32_t f2tf32(float f) {
    uint32_t u;
    asm("cvt.rna.tf32.f32 %0, %1;" : "=r"(u) : "f"(f));
    return u;
}

__device__ __forceinline__ void mma_tf32(float* d, const uint32_t* a,
                                         uint32_t b0, uint32_t b1) {
    asm volatile(
        "mma.sync.aligned.m16n8k8.row.col.f32.tf32.tf32.f32 "
        "{%0,%1,%2,%3}, {%4,%5,%6,%7}, {%8,%9}, {%0,%1,%2,%3};\n"
        : "+f"(d[0]), "+f"(d[1]), "+f"(d[2]), "+f"(d[3])
        : "r"(a[0]), "r"(a[1]), "r"(a[2]), "r"(a[3]), "r"(b0), "r"(b1));
}

// ---------------------------------------------------------------------------
// TF32 tensor-core GEMM (round-5/6 proven config: 256 thr, 8 warps 2m x 4n,
// warp tile 64x32, BK=32).  C[m,n] = sum_k A[m,k]*W[n,k] + bias[n]
// ---------------------------------------------------------------------------
__global__ __launch_bounds__(256) void gemm_tf32(const float* __restrict__ A_in,
                                                 const float* __restrict__ W,
                                                 const float* __restrict__ bias,
                                                 float* __restrict__ C_out,
                                                 int sel)
{
    __shared__ float As[128][36];
    __shared__ float Ws[128][36];

    const int K = DMODEL;
    const float* A = (sel == 3) ? g_attn : A_in;
    float* C;
    if (sel == 0)      C = g_q;
    else if (sel == 1) C = g_k;
    else if (sel == 2) C = g_v;
    else               C = C_out;

    const int tid  = threadIdx.x;
    const int w    = tid >> 5;
    const int lane = tid & 31;
    const int g    = lane >> 2;
    const int q    = lane & 3;
    const int wm   = (w & 1) * 64;
    const int wn   = (w >> 1) * 32;

    const int m0 = blockIdx.y * 128;
    const int n0 = blockIdx.x * 128;

    const float* Aptr = A + (size_t)m0 * K;
    const float* Wptr = W + (size_t)n0 * K;

    int ld_row[4], ld_c4[4];
#pragma unroll
    for (int i = 0; i < 4; i++) {
        int idx = tid + i * 256;
        ld_row[i] = idx >> 3;
        ld_c4[i]  = (idx & 7) * 4;
    }

    float acc[4][4][4];
#pragma unroll
    for (int mi = 0; mi < 4; mi++)
#pragma unroll
        for (int nj = 0; nj < 4; nj++)
#pragma unroll
            for (int c = 0; c < 4; c++) acc[mi][nj][c] = 0.0f;

    float4 pa[4], pw[4];
#pragma unroll
    for (int i = 0; i < 4; i++) {
        pa[i] = *reinterpret_cast<const float4*>(Aptr + (size_t)ld_row[i] * K + ld_c4[i]);
        pw[i] = *reinterpret_cast<const float4*>(Wptr + (size_t)ld_row[i] * K + ld_c4[i]);
    }

    for (int kt = 0; kt < K; kt += 32) {
#pragma unroll
        for (int i = 0; i < 4; i++) {
            float4 a = pa[i], t;
            t.x = __uint_as_float(f2tf32(a.x));
            t.y = __uint_as_float(f2tf32(a.y));
            t.z = __uint_as_float(f2tf32(a.z));
            t.w = __uint_as_float(f2tf32(a.w));
            *reinterpret_cast<float4*>(&As[ld_row[i]][ld_c4[i]]) = t;
            float4 b = pw[i];
            t.x = __uint_as_float(f2tf32(b.x));
            t.y = __uint_as_float(f2tf32(b.y));
            t.z = __uint_as_float(f2tf32(b.z));
            t.w = __uint_as_float(f2tf32(b.w));
            *reinterpret_cast<float4*>(&Ws[ld_row[i]][ld_c4[i]]) = t;
        }
        __syncthreads();

        if (kt + 32 < K) {
#pragma unroll
            for (int i = 0; i < 4; i++) {
                pa[i] = *reinterpret_cast<const float4*>(
                    Aptr + (size_t)ld_row[i] * K + kt + 32 + ld_c4[i]);
                pw[i] = *reinterpret_cast<const float4*>(
                    Wptr + (size_t)ld_row[i] * K + kt + 32 + ld_c4[i]);
            }
        }

#pragma unroll
        for (int kc = 0; kc < 4; kc++) {
            const int k0 = kc * 8;
            uint32_t a[4][4];
#pragma unroll
            for (int mi = 0; mi < 4; mi++) {
                int r = wm + mi * 16;
                a[mi][0] = __float_as_uint(As[r + g][k0 + q]);
                a[mi][1] = __float_as_uint(As[r + 8 + g][k0 + q]);
                a[mi][2] = __float_as_uint(As[r + g][k0 + q + 4]);
                a[mi][3] = __float_as_uint(As[r + 8 + g][k0 + q + 4]);
            }
            uint32_t b[4][2];
#pragma unroll
            for (int nj = 0; nj < 4; nj++) {
                int bn = wn + nj * 8;
                b[nj][0] = __float_as_uint(Ws[bn + g][k0 + q]);
                b[nj][1] = __float_as_uint(Ws[bn + g][k0 + q + 4]);
            }
#pragma unroll
            for (int mi = 0; mi < 4; mi++)
#pragma unroll
                for (int nj = 0; nj < 4; nj++)
                    mma_tf32(acc[mi][nj], a[mi], b[nj][0], b[nj][1]);
        }
        __syncthreads();
    }

    float bn_[4][2];
#pragma unroll
    for (int nj = 0; nj < 4; nj++) {
        int cn = n0 + wn + nj * 8 + 2 * q;
        bn_[nj][0] = bias[cn];
        bn_[nj][1] = bias[cn + 1];
    }

#pragma unroll
    for (int nj = 0; nj < 4; nj++) {
        int cn = n0 + wn + nj * 8 + 2 * q;
#pragma unroll
        for (int mi = 0; mi < 4; mi++) {
#pragma unroll
            for (int rr = 0; rr < 2; rr++) {
                int m = m0 + wm + mi * 16 + g + rr * 8;
                float2 v = make_float2(acc[mi][nj][rr * 2 + 0] + bn_[nj][0],
                                       acc[mi][nj][rr * 2 + 1] + bn_[nj][1]);
                if (sel <= 2) {
                    int h_ = cn >> 6;
                    int d_ = cn & 63;
                    int b_ = m >> 11, l_ = m & 2047;
                    *reinterpret_cast<float2*>(
                        C + (((size_t)(b_ * NHEAD + h_)) * SEQLEN + l_) * HEADDIM + d_) = v;
                } else {
                    *reinterpret_cast<float2*>(C + (size_t)m * DMODEL + cn) = v;
                }
            }
        }
    }
}

// ---------------------------------------------------------------------------
// RoPE pre-pass: rotate g_q (with 1/8 scale folded) and g_k in place.
// ---------------------------------------------------------------------------
__global__ __launch_bounds__(256) void rope_kernel()
{
    int idx = blockIdx.x * 256 + threadIdx.x;
    int d  = idx & 31;
    int l  = (idx >> 5) & (SEQLEN - 1);
    int bh = idx >> 16;
    size_t base = ((size_t)bh * SEQLEN + l) * HEADDIM;

    float invf = __expf(-(float)d * (9.210340371976184f / 32.0f));
    float sn, cs;
    sincosf((float)l * invf, &sn, &cs);

    float q1 = g_q[base + d], q2 = g_q[base + d + 32];
    g_q[base + d]      = (q1 * cs - q2 * sn) * 0.125f;
    g_q[base + d + 32] = (q2 * cs + q1 * sn) * 0.125f;

    float k1 = g_k[base + d], k2 = g_k[base + d + 32];
    g_k[base + d]      = k1 * cs - k2 * sn;
    g_k[base + d + 32] = k2 * cs + k1 * sn;
}

// ---------------------------------------------------------------------------
// Flash attention, tf32 mma, RoPE precomputed.
// Grid: (L/128, B*H). Block: 256 threads (8 warps), 1 m-frag per warp.
// Paired smem layouts with VECTORIZED stores:
//   Kp: pair (K[c][kc8+q], K[c][kc8+q+4]) at f2 Kp[c][kc*4+q], row 36 f2 (72 fl)
//   Vp: pair (V[kc8+q][c], V[kc8+q+4][c]) at f2 Vp[kc*4+q][c], row 68 f2 (136 fl)
// B-frag = one LDS.64; producer does 2x LDG.64 + 1x STS.128 (conflict-free).
// ---------------------------------------------------------------------------
__global__ __launch_bounds__(256, 2) void attn_mma_kernel()
{
    __shared__ float smem_all[64 * 72 + 32 * 136];   // 8960 floats = 35840 B
    float (*Qs)[68] = (float(*)[68])smem_all;        // staging: 128*68 = 8704 ok
    float* Kbase = smem_all;                         // K pairs: 64 rows x 72 floats
    float* Vbase = smem_all + 64 * 72;               // V pairs: 32 rows x 136 floats

    const int tid  = threadIdx.x;
    const int w    = tid >> 5;
    const int lane = tid & 31;
    const int g    = lane >> 2;
    const int q    = lane & 3;

    const int bh = blockIdx.y;
    const int b_ = bh >> 4;
    const int h_ = bh & 15;
    const int q0 = blockIdx.x * 128;

    const float* Qg = g_q + (size_t)bh * SEQLEN * HEADDIM;
    const float* Kg = g_k + (size_t)bh * SEQLEN * HEADDIM;
    const float* Vg = g_v + (size_t)bh * SEQLEN * HEADDIM;

    // ---- Load Q tile [128][64] (RoPE'd + scaled) ----
#pragma unroll
    for (int i = 0; i < 8; i++) {
        int idx = tid + i * 256;
        int r = idx >> 4;
        int cv = (idx & 15) * 4;
        float4 v = *reinterpret_cast<const float4*>(Qg + (size_t)(q0 + r) * HEADDIM + cv);
        Qs[r][cv + 0] = v.x; Qs[r][cv + 1] = v.y;
        Qs[r][cv + 2] = v.z; Qs[r][cv + 3] = v.w;
    }
    __syncthreads();

    // ---- Extract Q A-fragment (1 m-frag per warp) ----
    uint32_t aq[8][4];
    {
        int row0 = w * 16 + g;
#pragma unroll
        for (int kc = 0; kc < 8; kc++) {
            int c0 = kc * 8 + q;
            aq[kc][0] = f2tf32(Qs[row0][c0]);
            aq[kc][1] = f2tf32(Qs[row0 + 8][c0]);
            aq[kc][2] = f2tf32(Qs[row0][c0 + 4]);
            aq[kc][3] = f2tf32(Qs[row0 + 8][c0 + 4]);
        }
    }

    float o[8][4];
    float mA = -INFINITY, mB = -INFINITY, lA = 0.0f, lB = 0.0f;
#pragma unroll
    for (int n = 0; n < 8; n++)
#pragma unroll
        for (int c = 0; c < 4; c++) o[n][c] = 0.0f;

    for (int kk = 0; kk < 32; kk++) {
        const int kv0 = kk * 64;
        __syncthreads();   // kk=0: Q frags extracted; kk>0: prior mma reads done

        // ---- K tile: pair columns (d, d+4). 1024 tasks across 256 thr. ----
#pragma unroll
        for (int i = 0; i < 4; i++) {
            int idx = tid + i * 256;
            int r  = idx >> 4;           // 0..63
            int kc = (idx >> 1) & 7;     // 0..7
            int h  = idx & 1;            // q-pair half: q = 2h, 2h+1
            const float* src = Kg + (size_t)(kv0 + r) * HEADDIM + kc * 8 + 2 * h;
            float2 a = *reinterpret_cast<const float2*>(src);
            float2 b = *reinterpret_cast<const float2*>(src + 4);
            float4 t;
            t.x = __uint_as_float(f2tf32(a.x));
            t.y = __uint_as_float(f2tf32(b.x));
            t.z = __uint_as_float(f2tf32(a.y));
            t.w = __uint_as_float(f2tf32(b.y));
            *reinterpret_cast<float4*>(&Kbase[r * 72 + kc * 8 + 4 * h]) = t;
        }
        // ---- V tile: pair rows (r, r+4). 1024 tasks. ----
#pragma unroll
        for (int i = 0; i < 4; i++) {
            int idx = tid + i * 256;
            int c2 = idx & 31;           // float2 column: floats 2*c2
            int rp = idx >> 5;           // 0..31: kc = rp>>2, q = rp&3
            int row = ((rp >> 2) << 3) + (rp & 3);
            const float* src = Vg + (size_t)(kv0 + row) * HEADDIM + 2 * c2;
            float2 a = *reinterpret_cast<const float2*>(src);
            float2 b = *reinterpret_cast<const float2*>(src + 4 * HEADDIM);
            float4 t;
            t.x = __uint_as_float(f2tf32(a.x));
            t.y = __uint_as_float(f2tf32(b.x));
            t.z = __uint_as_float(f2tf32(a.y));
            t.w = __uint_as_float(f2tf32(b.y));
            *reinterpret_cast<float4*>(&Vbase[rp * 136 + 4 * c2]) = t;
        }
        __syncthreads();

        // ---- S = Q . K^T (B-frag = one LDS.64) ----
        float s[8][4];
#pragma unroll
        for (int n = 0; n < 8; n++)
#pragma unroll
            for (int c = 0; c < 4; c++) s[n][c] = 0.0f;

#pragma unroll
        for (int n = 0; n < 8; n++) {
#pragma unroll
            for (int kc = 0; kc < 8; kc++) {
                float2 bb = *reinterpret_cast<const float2*>(
                    &Kbase[(n * 8 + g) * 72 + kc * 8 + 2 * q]);
                mma_tf32(s[n], aq[kc], __float_as_uint(bb.x), __float_as_uint(bb.y));
            }
        }

        // ---- Online softmax ----
        {
            float mxA = -1e30f, mxB = -1e30f;
#pragma unroll
            for (int n = 0; n < 8; n++) {
                mxA = fmaxf(mxA, fmaxf(s[n][0], s[n][1]));
                mxB = fmaxf(mxB, fmaxf(s[n][2], s[n][3]));
            }
            mxA = fmaxf(mxA, __shfl_xor_sync(0xffffffffu, mxA, 1));
            mxA = fmaxf(mxA, __shfl_xor_sync(0xffffffffu, mxA, 2));
            mxB = fmaxf(mxB, __shfl_xor_sync(0xffffffffu, mxB, 1));
            mxB = fmaxf(mxB, __shfl_xor_sync(0xffffffffu, mxB, 2));
            float mnA = fmaxf(mA, mxA);
            float mnB = fmaxf(mB, mxB);
            float cA = __expf(mA - mnA);
            float cB = __expf(mB - mnB);
            float rsA = 0.0f, rsB = 0.0f;
#pragma unroll
            for (int n = 0; n < 8; n++) {
                s[n][0] = __expf(s[n][0] - mnA); rsA += s[n][0];
                s[n][1] = __expf(s[n][1] - mnA); rsA += s[n][1];
                s[n][2] = __expf(s[n][2] - mnB); rsB += s[n][2];
                s[n][3] = __expf(s[n][3] - mnB); rsB += s[n][3];
                o[n][0] *= cA; o[n][1] *= cA;
                o[n][2] *= cB; o[n][3] *= cB;
            }
            rsA += __shfl_xor_sync(0xffffffffu, rsA, 1);
            rsA += __shfl_xor_sync(0xffffffffu, rsA, 2);
            rsB += __shfl_xor_sync(0xffffffffu, rsB, 1);
            rsB += __shfl_xor_sync(0xffffffffu, rsB, 2);
            lA = lA * cA + rsA; mA = mnA;
            lB = lB * cB + rsB; mB = mnB;
        }

        // ---- O += P . V : P A-frags via shfl; V B-frag = one LDS.64 ----
        const int src0 = (g << 2) + (q >> 1);
        const int src1 = src0 + 2;
        const bool odd = (q & 1);
#pragma unroll
        for (int kc = 0; kc < 8; kc++) {
            uint32_t ap[4];
            float v00 = __shfl_sync(0xffffffffu, s[kc][0], src0);
            float v01 = __shfl_sync(0xffffffffu, s[kc][1], src0);
            float v02 = __shfl_sync(0xffffffffu, s[kc][2], src0);
            float v03 = __shfl_sync(0xffffffffu, s[kc][3], src0);
            float v10 = __shfl_sync(0xffffffffu, s[kc][0], src1);
            float v11 = __shfl_sync(0xffffffffu, s[kc][1], src1);
            float v12 = __shfl_sync(0xffffffffu, s[kc][2], src1);
            float v13 = __shfl_sync(0xffffffffu, s[kc][3], src1);
            ap[0] = f2tf32(odd ? v01 : v00);
            ap[1] = f2tf32(odd ? v03 : v02);
            ap[2] = f2tf32(odd ? v11 : v10);
            ap[3] = f2tf32(odd ? v13 : v12);
#pragma unroll
            for (int n = 0; n < 8; n++) {
                float2 bb = *reinterpret_cast<const float2*>(
                    &Vbase[(kc * 4 + q) * 136 + 2 * (n * 8 + g)]);
                mma_tf32(o[n], ap, __float_as_uint(bb.x), __float_as_uint(bb.y));
            }
        }
    }

    // ---- Epilogue: normalize, write [B,L,H*hd] ----
    {
        float iA = 1.0f / lA;
        float iB = 1.0f / lB;
        int row0 = q0 + w * 16 + g;
#pragma unroll
        for (int n = 0; n < 8; n++) {
            int col = n * 8 + 2 * q;
            float2 r0v = make_float2(o[n][0] * iA, o[n][1] * iA);
            float2 r1v = make_float2(o[n][2] * iB, o[n][3] * iB);
            *reinterpret_cast<float2*>(
                g_attn + ((size_t)(b_ * SEQLEN + row0) * NHEAD + h_) * HEADDIM + col) = r0v;
            *reinterpret_cast<float2*>(
                g_attn + ((size_t)(b_ * SEQLEN + row0 + 8) * NHEAD + h_) * HEADDIM + col) = r1v;
        }
    }
}

// ---------------------------------------------------------------------------
extern "C" void kernel_launch(void* const* d_in, const int* in_sizes, int n_in,
                              void* d_out, int out_size)
{
    const float* x  = (const float*)d_in[0];
    const float* Wq = (const float*)d_in[1];
    const float* bq = (const float*)d_in[2];
    const float* Wk = (const float*)d_in[3];
    const float* bk = (const float*)d_in[4];
    const float* Wv = (const float*)d_in[5];
    const float* bv = (const float*)d_in[6];
    const float* Wo = (const float*)d_in[7];
    const float* bo = (const float*)d_in[8];
    float* out = (float*)d_out;

    dim3 ggrid(DMODEL / 128, MROWS / 128);   // (8, 64)
    gemm_tf32<<<ggrid, 256>>>(x, Wq, bq, nullptr, 0);
    gemm_tf32<<<ggrid, 256>>>(x, Wk, bk, nullptr, 1);
    gemm_tf32<<<ggrid, 256>>>(x, Wv, bv, nullptr, 2);

    rope_kernel<<<(BATCH * NHEAD * SEQLEN * 32) / 256, 256>>>();

    attn_mma_kernel<<<dim3(SEQLEN / 128, BATCH * NHEAD), 256>>>();

    gemm_tf32<<<ggrid, 256>>>(nullptr, Wo, bo, out, 3);
}